// round 15
// baseline (speedup 1.0000x reference)
#include <cuda_runtime.h>
#include <cuda_fp16.h>
#include <cstdint>

#define NROWS 2000000
#define D 128
#define NSEG 4096
#define NTILES (NROWS / 128)          // 15625

// ---- k1 dynamic smem layout (bytes) ----
#define WS_OFF    0
#define XH0_OFF   34816
#define XH1_OFF   69632
#define MISC_OFF  104448
#define SMEM_TOTAL (104448 + 5120)

#define WSTR 136   // half stride of ws/xh rows (272 B)

// ---- scratch (no allocations allowed) ----
__device__ float    g_s[NROWS];
__device__ float    g_segsum[NSEG];
__device__ unsigned g_segmaxb[NSEG];
__device__ int      g_is64;
__device__ __half   g_w1h[D * D];                 // W1^T half
__device__ __half   g_xh[(size_t)NROWS * D];      // fp16 mirror of x (512 MB)

// ---- helpers ----
__device__ __forceinline__ int seg_at(const void* p, int is64, long long i) {
    int v = is64 ? (int)((const long long*)p)[i] : ((const int*)p)[i];
    return min(max(v, 0), NSEG - 1);
}
__device__ __forceinline__ unsigned fmap(float f) {
    unsigned u = __float_as_uint(f);
    return (u & 0x80000000u) ? ~u : (u | 0x80000000u);
}
__device__ __forceinline__ float funmap(unsigned m) {
    return (m & 0x80000000u) ? __uint_as_float(m ^ 0x80000000u)
                             : __uint_as_float(~m);
}
__device__ __forceinline__ float tanh_hw(float v) {
    float r;
    asm("tanh.approx.f32 %0, %1;" : "=f"(r) : "f"(v));
    return r;
}
__device__ __forceinline__ void cp16(unsigned saddr, const void* g) {
    asm volatile("cp.async.cg.shared.global [%0], [%1], 16;\n"
                 :: "r"(saddr), "l"(g) : "memory");
}
__device__ __forceinline__ void cp_commit() {
    asm volatile("cp.async.commit_group;\n" ::: "memory");
}
__device__ __forceinline__ void cp_wait0() {
    asm volatile("cp.async.wait_group 0;\n" ::: "memory");
}
__device__ __forceinline__ void ldsm4(unsigned r[4], unsigned saddr) {
    asm volatile("ldmatrix.sync.aligned.m8n8.x4.shared.b16 {%0,%1,%2,%3}, [%4];\n"
                 : "=r"(r[0]), "=r"(r[1]), "=r"(r[2]), "=r"(r[3]) : "r"(saddr));
}
__device__ __forceinline__ void mma16816(float c[4], const unsigned a[4],
                                         unsigned b0, unsigned b1) {
    asm volatile(
        "mma.sync.aligned.m16n8k16.row.col.f32.f16.f16.f32 "
        "{%0,%1,%2,%3}, {%4,%5,%6,%7}, {%8,%9}, {%0,%1,%2,%3};\n"
        : "+f"(c[0]), "+f"(c[1]), "+f"(c[2]), "+f"(c[3])
        : "r"(a[0]), "r"(a[1]), "r"(a[2]), "r"(a[3]), "r"(b0), "r"(b1));
}

// ---------------------------------------------------------------------------
// k0: zero out + seg scratch; detect idx dtype; pack W1^T as half (n-major).
// ---------------------------------------------------------------------------
__global__ void k0_init(float* __restrict__ out, const void* __restrict__ idxp,
                        const float* __restrict__ W1) {
    long long i = (long long)blockIdx.x * blockDim.x + threadIdx.x;
    if (i < NSEG * D) out[i] = 0.0f;
    if (i < NSEG) { g_segsum[i] = 0.0f; g_segmaxb[i] = 0u; }
    if (i < D * D) {
        int n = (int)(i / D), k = (int)(i % D);
        g_w1h[i] = __float2half_rn(W1[(size_t)k * D + n]);
    }
    if (i == 0) {
        const long long* p64 = (const long long*)idxp;
        long long a = p64[NROWS / 4];
        long long b = p64[NROWS / 8];
        g_is64 = (a >= 0 && a < NSEG && b >= 0 && b < NSEG) ? 1 : 0;
    }
}

// ---------------------------------------------------------------------------
// k1: persistent fp16-mma MLP (R9/R14 shape) + fp16 x mirror STG
// (coalesced full-row 256B warp stores; measured +53us in R13).
// ---------------------------------------------------------------------------
__global__ __launch_bounds__(512, 1)
void k1_mlp(const float* __restrict__ x,
            const float* __restrict__ b1, const float* __restrict__ W2,
            const float* __restrict__ b2, const void* __restrict__ idxp)
{
    extern __shared__ char sm[];
    float2* bwp = (float2*)(sm + MISC_OFF);
    float (*sred2)[4][128] = (float(*)[4][128])(sm + MISC_OFF + 1024);

    const unsigned s_base  = (unsigned)__cvta_generic_to_shared(sm);
    const unsigned s_ws    = s_base + WS_OFF;
    const unsigned s_xh[2] = { s_base + XH0_OFF, s_base + XH1_OFF };

    const int tid  = threadIdx.x;
    const int lane = tid & 31;
    const int warp = tid >> 5;
    const int gid  = lane >> 2;
    const int tig  = lane & 3;
    const int m0   = (warp & 3) * 32;
    const int n0   = (warp >> 2) * 32;
    const int ngrp = warp >> 2;
    const int grid = gridDim.x;
    const int cta  = blockIdx.x;
    const int n_t  = (NTILES - cta + grid - 1) / grid;
    const int is64 = g_is64;

    const int cv_r0 = tid >> 5;
    const int cv_cc = tid & 31;

    const unsigned a_off = (unsigned)((m0 + (lane & 15)) * (WSTR * 2) + ((lane >> 4) * 16));
    const unsigned b_off = (unsigned)((n0 + (lane & 7) + ((lane >> 4) << 3)) * (WSTR * 2)
                                      + (((lane >> 3) & 1) * 16));

    if (tid < 128) bwp[tid] = make_float2(b1[tid], W2[tid]);
    const float b2v = b2[0];

    if (n_t == 0) return;

    // ---- prologue: ws via cp.async (one-time), tile0 via LDG->cvt->STS+STG ----
#pragma unroll
    for (int c = 0; c < 4; c++) {
        int q = tid + c * 512;
        int r = q >> 4, cc = q & 15;
        cp16(s_ws + (unsigned)(r * (WSTR * 2) + cc * 16),
             g_w1h + (size_t)r * D + cc * 8);
    }
    cp_commit();
    {
        const size_t tb0 = (size_t)cta * 128;
        const float4* xb = (const float4*)(x + tb0 * D);
        float4 rv[8];
#pragma unroll
        for (int j = 0; j < 8; j++) rv[j] = xb[tid + j * 512];
        cp_wait0();
        __syncthreads();
#pragma unroll
        for (int j = 0; j < 8; j++) {
            __half2 h0 = __floats2half2_rn(rv[j].x, rv[j].y);
            __half2 h1 = __floats2half2_rn(rv[j].z, rv[j].w);
            uint2 u = { *(unsigned*)&h0, *(unsigned*)&h1 };
            *(uint2*)(sm + XH0_OFF + (size_t)(cv_r0 + 16 * j) * (WSTR * 2) + cv_cc * 8) = u;
            *(uint2*)(&g_xh[(tb0 + cv_r0 + 16 * j) * D + cv_cc * 4]) = u;
        }
        __syncthreads();
    }

    for (int i = 0; i < n_t; i++) {
        const int b = i & 1;
        const int ph = i & 1;
        const unsigned xa = s_xh[b] + a_off;
        const unsigned bb = s_ws + b_off;
        const bool have_next = (i + 1 < n_t);
        const size_t row0 = ((size_t)cta + (size_t)i * grid) * 128;
        const size_t tb1 = ((size_t)cta + (size_t)(i + 1) * grid) * 128;

        // ---- prefetch tile i+1 x-data and tile i idx (hides under MMA) ----
        float4 rv[8];
        if (have_next) {
            const float4* xn = (const float4*)(x + tb1 * D);
#pragma unroll
            for (int j = 0; j < 8; j++) rv[j] = xn[tid + j * 512];
        }
        int myseg = 0;
        if (tid < 128) myseg = seg_at(idxp, is64, (long long)(row0 + tid));

        // ---- mainloop: 8 k16 steps, warp tile m32 x n32 ----
        float c[2][4][4];
#pragma unroll
        for (int mi = 0; mi < 2; mi++)
#pragma unroll
            for (int nj = 0; nj < 4; nj++)
#pragma unroll
                for (int r = 0; r < 4; r++) c[mi][nj][r] = 0.0f;

#pragma unroll
        for (int k0 = 0; k0 < 8; k0++) {
            unsigned af[2][4], bf[2][4];
            ldsm4(af[0], xa + k0 * 32);
            ldsm4(af[1], xa + 16 * (WSTR * 2) + k0 * 32);
            ldsm4(bf[0], bb + k0 * 32);
            ldsm4(bf[1], bb + 16 * (WSTR * 2) + k0 * 32);
#pragma unroll
            for (int mi = 0; mi < 2; mi++)
#pragma unroll
                for (int nj2 = 0; nj2 < 2; nj2++) {
                    mma16816(c[mi][nj2 * 2],     af[mi], bf[nj2][0], bf[nj2][1]);
                    mma16816(c[mi][nj2 * 2 + 1], af[mi], bf[nj2][2], bf[nj2][3]);
                }
        }

        // ---- store tile i+1 into xh[b^1] + fp16 mirror STG ----
        if (have_next) {
            char* dst = sm + (b ? XH0_OFF : XH1_OFF);
#pragma unroll
            for (int j = 0; j < 8; j++) {
                __half2 h0 = __floats2half2_rn(rv[j].x, rv[j].y);
                __half2 h1 = __floats2half2_rn(rv[j].z, rv[j].w);
                uint2 u = { *(unsigned*)&h0, *(unsigned*)&h1 };
                *(uint2*)(dst + (size_t)(cv_r0 + 16 * j) * (WSTR * 2) + cv_cc * 8) = u;
                *(uint2*)(&g_xh[(tb1 + cv_r0 + 16 * j) * D + cv_cc * 4]) = u;
            }
        }

        // ---- epilogue: bias + hw-tanh + dot(W2) -> per-row partials ----
        float b1v[4][2], w2v[4][2];
#pragma unroll
        for (int nj = 0; nj < 4; nj++)
#pragma unroll
            for (int cc = 0; cc < 2; cc++) {
                float2 bw = bwp[n0 + nj * 8 + tig * 2 + cc];
                b1v[nj][cc] = bw.x;
                w2v[nj][cc] = bw.y;
            }
        float rp[4] = {0.0f, 0.0f, 0.0f, 0.0f};
#pragma unroll
        for (int mi = 0; mi < 2; mi++)
#pragma unroll
            for (int nj = 0; nj < 4; nj++)
#pragma unroll
                for (int r = 0; r < 4; r++) {
                    float h = tanh_hw(c[mi][nj][r] + b1v[nj][r & 1]);
                    rp[mi * 2 + (r >> 1)] = fmaf(h, w2v[nj][r & 1], rp[mi * 2 + (r >> 1)]);
                }
#pragma unroll
        for (int q = 0; q < 4; q++) {
            rp[q] += __shfl_xor_sync(0xffffffffu, rp[q], 1);
            rp[q] += __shfl_xor_sync(0xffffffffu, rp[q], 2);
        }
        if (tig == 0) {
#pragma unroll
            for (int q = 0; q < 4; q++) {
                int row = m0 + (q >> 1) * 16 + (q & 1) * 8 + gid;
                sred2[ph][ngrp][row] = rp[q];
            }
        }
        __syncthreads();   // the ONLY barrier per tile

        // ---- score out: sum 4 banks, fire-and-forget segment atomicMax ----
        if (tid < 128) {
            float sv = sred2[ph][0][tid] + sred2[ph][1][tid]
                     + sred2[ph][2][tid] + sred2[ph][3][tid] + b2v;
            g_s[row0 + tid] = sv;
            atomicMax(&g_segmaxb[myseg], fmap(sv));
        }
    }
}

// ---------------------------------------------------------------------------
// k2: e = exp(s - seg_max[idx]); smem bucket aggregation of seg_sum.
// ---------------------------------------------------------------------------
__global__ __launch_bounds__(256) void k2_exp(
    const void* __restrict__ idxp, float* __restrict__ e_out)
{
    __shared__ float buck[2048];
    const int tid = threadIdx.x;
    const long long base = (long long)blockIdx.x * 2048;
    const long long last = min(base + 2047LL, (long long)NROWS - 1);
    const int is64 = g_is64;
    const int seg_lo = seg_at(idxp, is64, base);
    const int seg_hi = seg_at(idxp, is64, last);
    const int range = seg_hi - seg_lo + 1;
    const bool use_smem = (range > 0 && range <= 2048);
    if (use_smem)
        for (int k = tid; k < range; k += 256) buck[k] = 0.0f;
    __syncthreads();

    for (int j = tid; j < 2048; j += 256) {
        long long r = base + j;
        if (r >= NROWS) break;
        int seg = seg_at(idxp, is64, r);
        float smax = funmap(g_segmaxb[seg]);
        float e = __expf(g_s[r] - smax);
        e_out[r] = e;
        if (use_smem) atomicAdd(&buck[seg - seg_lo], e);
        else          atomicAdd(&g_segsum[seg], e);
    }
    __syncthreads();

    if (use_smem)
        for (int k = tid; k < range; k += 256) {
            float v = buck[k];
            if (v != 0.0f) atomicAdd(&g_segsum[seg_lo + k], v);
        }
}

// ---------------------------------------------------------------------------
// k3: phase 1 (alpha) = frozen code. Phase 2 reads the fp16 mirror with
// FULL-WIDTH warp requests: two 64-thread teams, each thread owns a half2
// column pair and issues one LDG.32 per row -> 32x4B = 128B/warp request
// (identical shape to the measured-good fp32 loop, half the bytes).
// ---------------------------------------------------------------------------
__global__ __launch_bounds__(128) void k3_agg(
    const void* __restrict__ idxp,
    float* __restrict__ alpha, float* __restrict__ out)
{
    __shared__ float sa[512];
    __shared__ int   sseg[512];
    const int tid = threadIdx.x;
    const long long base = (long long)blockIdx.x * 512;
    const int nrows = (int)min(512LL, (long long)NROWS - base);
    const int is64 = g_is64;

    for (int j = tid; j < nrows; j += 128) {
        int seg = seg_at(idxp, is64, base + j);
        float e = alpha[base + j];
        float a = __fdividef(e, g_segsum[seg] + 1e-16f);
        sa[j] = a;
        sseg[j] = seg;
        alpha[base + j] = a;
    }
    __syncthreads();

    const int team = tid >> 6;           // 0: rows [0,256), 1: rows [256,512)
    const int l64  = tid & 63;           // half2 column pair index
    const int r0   = team * 256;
    const int cnt  = min(256, nrows - r0);
    if (cnt <= 0) return;

    const __half2* xp = (const __half2*)g_xh + (size_t)(base + r0) * 64 + l64;
    const float*   sap = sa + r0;
    const int*     sgp = sseg + r0;
    const int      c0  = l64 * 2;

    if (sgp[0] == sgp[cnt - 1]) {
        // fast path: whole team range in one segment
        float a0 = 0.0f, a1 = 0.0f;
        for (int j = 0; j < cnt; j++) {
            float2 f = __half22float2(xp[(size_t)j * 64]);
            a0 = fmaf(f.x, sap[j], a0);
            a1 = fmaf(f.y, sap[j], a1);
        }
        atomicAdd(&out[(size_t)sgp[0] * D + c0], a0);
        atomicAdd(&out[(size_t)sgp[0] * D + c0 + 1], a1);
    } else {
        float a0 = 0.0f, a1 = 0.0f;
        int cur = sgp[0];
        for (int j = 0; j < cnt; j++) {
            int sg = sgp[j];
            if (sg != cur) {
                atomicAdd(&out[(size_t)cur * D + c0], a0);
                atomicAdd(&out[(size_t)cur * D + c0 + 1], a1);
                a0 = a1 = 0.0f;
                cur = sg;
            }
            float2 f = __half22float2(xp[(size_t)j * 64]);
            a0 = fmaf(f.x, sap[j], a0);
            a1 = fmaf(f.y, sap[j], a1);
        }
        atomicAdd(&out[(size_t)cur * D + c0], a0);
        atomicAdd(&out[(size_t)cur * D + c0 + 1], a1);
    }
}

// ---------------------------------------------------------------------------
extern "C" void kernel_launch(void* const* d_in, const int* in_sizes, int n_in,
                              void* d_out, int out_size)
{
    const float* x  = (const float*)d_in[0];
    const float* W1 = (const float*)d_in[1];
    const float* b1 = (const float*)d_in[2];
    const float* W2 = (const float*)d_in[3];
    const float* b2 = (const float*)d_in[4];
    const void*  idxp = d_in[5];

    float* outp  = (float*)d_out;          // (4096, 128)
    float* alpha = outp + NSEG * D;        // (N, 1) -- holds e between k2/k3

    static int sms = 0;
    if (!sms) {
        cudaDeviceGetAttribute(&sms, cudaDevAttrMultiProcessorCount, 0);
        cudaFuncSetAttribute(k1_mlp, cudaFuncAttributeMaxDynamicSharedMemorySize,
                             SMEM_TOTAL);
    }

    k0_init<<<(NSEG * D + 255) / 256, 256>>>(outp, idxp, W1);
    k1_mlp <<<sms, 512, SMEM_TOTAL>>>(x, b1, W2, b2, idxp);
    k2_exp <<<(NROWS + 2047) / 2048, 256>>>(idxp, alpha);
    k3_agg <<<(NROWS + 511) / 512, 128>>>(idxp, alpha, outp);
}

// round 16
// speedup vs baseline: 1.1693x; 1.1693x over previous
#include <cuda_runtime.h>
#include <cuda_fp16.h>
#include <cstdint>

#define NROWS 2000000
#define D 128
#define NSEG 4096
#define NTILES (NROWS / 128)          // 15625

// ---- k1 dynamic smem layout (bytes) ----
// ws:    half Wt[128 n][136 half] (stride 272B)               34816
// xh[2]: half x  [128 r][136 half] (stride 272B)            2x34816
// misc:  bw float2[128] (1KB), sred2[2][4][128] (4KB)          5120
#define WS_OFF    0
#define XH0_OFF   34816
#define XH1_OFF   69632
#define MISC_OFF  104448
#define SMEM_TOTAL (104448 + 5120)

#define WSTR 136   // half stride of ws/xh rows (272 B)

// ---- scratch (no allocations allowed) ----
__device__ float    g_s[NROWS];
__device__ float    g_segsum[NSEG];
__device__ unsigned g_segmaxb[NSEG];
__device__ int      g_is64;
__device__ __half   g_w1h[D * D];   // W1^T as half: g_w1h[n*128+k] = W1[k][n]

// ---- helpers ----
__device__ __forceinline__ int seg_at(const void* p, int is64, long long i) {
    int v = is64 ? (int)((const long long*)p)[i] : ((const int*)p)[i];
    return min(max(v, 0), NSEG - 1);
}
__device__ __forceinline__ unsigned fmap(float f) {
    unsigned u = __float_as_uint(f);
    return (u & 0x80000000u) ? ~u : (u | 0x80000000u);
}
__device__ __forceinline__ float funmap(unsigned m) {
    return (m & 0x80000000u) ? __uint_as_float(m ^ 0x80000000u)
                             : __uint_as_float(~m);
}
__device__ __forceinline__ float tanh_hw(float v) {
    float r;
    asm("tanh.approx.f32 %0, %1;" : "=f"(r) : "f"(v));
    return r;
}
__device__ __forceinline__ void cp16(unsigned saddr, const void* g) {
    asm volatile("cp.async.cg.shared.global [%0], [%1], 16;\n"
                 :: "r"(saddr), "l"(g) : "memory");
}
__device__ __forceinline__ void cp_commit() {
    asm volatile("cp.async.commit_group;\n" ::: "memory");
}
__device__ __forceinline__ void cp_wait0() {
    asm volatile("cp.async.wait_group 0;\n" ::: "memory");
}
__device__ __forceinline__ void ldsm4(unsigned r[4], unsigned saddr) {
    asm volatile("ldmatrix.sync.aligned.m8n8.x4.shared.b16 {%0,%1,%2,%3}, [%4];\n"
                 : "=r"(r[0]), "=r"(r[1]), "=r"(r[2]), "=r"(r[3]) : "r"(saddr));
}
__device__ __forceinline__ void mma16816(float c[4], const unsigned a[4],
                                         unsigned b0, unsigned b1) {
    asm volatile(
        "mma.sync.aligned.m16n8k16.row.col.f32.f16.f16.f32 "
        "{%0,%1,%2,%3}, {%4,%5,%6,%7}, {%8,%9}, {%0,%1,%2,%3};\n"
        : "+f"(c[0]), "+f"(c[1]), "+f"(c[2]), "+f"(c[3])
        : "r"(a[0]), "r"(a[1]), "r"(a[2]), "r"(a[3]), "r"(b0), "r"(b1));
}

// ---------------------------------------------------------------------------
// k0: zero out + seg scratch; detect idx dtype; pack W1^T as half (n-major).
// ---------------------------------------------------------------------------
__global__ void k0_init(float* __restrict__ out, const void* __restrict__ idxp,
                        const float* __restrict__ W1) {
    long long i = (long long)blockIdx.x * blockDim.x + threadIdx.x;
    if (i < NSEG * D) out[i] = 0.0f;
    if (i < NSEG) { g_segsum[i] = 0.0f; g_segmaxb[i] = 0u; }
    if (i < D * D) {
        int n = (int)(i / D), k = (int)(i % D);
        g_w1h[i] = __float2half_rn(W1[(size_t)k * D + n]);
    }
    if (i == 0) {
        const long long* p64 = (const long long*)idxp;
        long long a = p64[NROWS / 4];
        long long b = p64[NROWS / 8];
        g_is64 = (a >= 0 && a < NSEG && b >= 0 && b < NSEG) ? 1 : 0;
    }
}

// ---------------------------------------------------------------------------
// k1: persistent fp16-mma MLP (512 thr, 16 warps, warp tile m32 x n32, one
// barrier/tile, phase-alternating sred2, fire-and-forget atomicMax).
// ---------------------------------------------------------------------------
__global__ __launch_bounds__(512, 1)
void k1_mlp(const float* __restrict__ x,
            const float* __restrict__ b1, const float* __restrict__ W2,
            const float* __restrict__ b2, const void* __restrict__ idxp)
{
    extern __shared__ char sm[];
    float2* bwp = (float2*)(sm + MISC_OFF);
    float (*sred2)[4][128] = (float(*)[4][128])(sm + MISC_OFF + 1024);

    const unsigned s_base  = (unsigned)__cvta_generic_to_shared(sm);
    const unsigned s_ws    = s_base + WS_OFF;
    const unsigned s_xh[2] = { s_base + XH0_OFF, s_base + XH1_OFF };

    const int tid  = threadIdx.x;
    const int lane = tid & 31;
    const int warp = tid >> 5;
    const int gid  = lane >> 2;
    const int tig  = lane & 3;
    const int m0   = (warp & 3) * 32;
    const int n0   = (warp >> 2) * 32;
    const int ngrp = warp >> 2;
    const int grid = gridDim.x;
    const int cta  = blockIdx.x;
    const int n_t  = (NTILES - cta + grid - 1) / grid;
    const int is64 = g_is64;

    const int cv_r0 = tid >> 5;
    const int cv_cc = tid & 31;

    const unsigned a_off = (unsigned)((m0 + (lane & 15)) * (WSTR * 2) + ((lane >> 4) * 16));
    const unsigned b_off = (unsigned)((n0 + (lane & 7) + ((lane >> 4) << 3)) * (WSTR * 2)
                                      + (((lane >> 3) & 1) * 16));

    if (tid < 128) bwp[tid] = make_float2(b1[tid], W2[tid]);
    const float b2v = b2[0];

    if (n_t == 0) return;

    // ---- prologue: ws via cp.async (one-time), tile0 via LDG->cvt->STS ----
#pragma unroll
    for (int c = 0; c < 4; c++) {
        int q = tid + c * 512;
        int r = q >> 4, cc = q & 15;
        cp16(s_ws + (unsigned)(r * (WSTR * 2) + cc * 16),
             g_w1h + (size_t)r * D + cc * 8);
    }
    cp_commit();
    {
        const float4* xb = (const float4*)(x + (size_t)cta * 128 * D);
        float4 rv[8];
#pragma unroll
        for (int j = 0; j < 8; j++) rv[j] = xb[tid + j * 512];
        cp_wait0();
        __syncthreads();
#pragma unroll
        for (int j = 0; j < 8; j++) {
            __half2 h0 = __floats2half2_rn(rv[j].x, rv[j].y);
            __half2 h1 = __floats2half2_rn(rv[j].z, rv[j].w);
            uint2 u = { *(unsigned*)&h0, *(unsigned*)&h1 };
            *(uint2*)(sm + XH0_OFF + (size_t)(cv_r0 + 16 * j) * (WSTR * 2) + cv_cc * 8) = u;
        }
        __syncthreads();
    }

    for (int i = 0; i < n_t; i++) {
        const int b = i & 1;
        const int ph = i & 1;
        const unsigned xa = s_xh[b] + a_off;
        const unsigned bb = s_ws + b_off;
        const bool have_next = (i + 1 < n_t);
        const size_t row0 = ((size_t)cta + (size_t)i * grid) * 128;

        // ---- prefetch tile i+1 x-data and tile i idx (hides under MMA) ----
        float4 rv[8];
        if (have_next) {
            const float4* xn = (const float4*)(x + ((size_t)cta + (size_t)(i + 1) * grid) * 128 * D);
#pragma unroll
            for (int j = 0; j < 8; j++) rv[j] = xn[tid + j * 512];
        }
        int myseg = 0;
        if (tid < 128) myseg = seg_at(idxp, is64, (long long)(row0 + tid));

        // ---- mainloop: 8 k16 steps, warp tile m32 x n32 ----
        float c[2][4][4];
#pragma unroll
        for (int mi = 0; mi < 2; mi++)
#pragma unroll
            for (int nj = 0; nj < 4; nj++)
#pragma unroll
                for (int r = 0; r < 4; r++) c[mi][nj][r] = 0.0f;

#pragma unroll
        for (int k0 = 0; k0 < 8; k0++) {
            unsigned af[2][4], bf[2][4];
            ldsm4(af[0], xa + k0 * 32);
            ldsm4(af[1], xa + 16 * (WSTR * 2) + k0 * 32);
            ldsm4(bf[0], bb + k0 * 32);
            ldsm4(bf[1], bb + 16 * (WSTR * 2) + k0 * 32);
#pragma unroll
            for (int mi = 0; mi < 2; mi++)
#pragma unroll
                for (int nj2 = 0; nj2 < 2; nj2++) {
                    mma16816(c[mi][nj2 * 2],     af[mi], bf[nj2][0], bf[nj2][1]);
                    mma16816(c[mi][nj2 * 2 + 1], af[mi], bf[nj2][2], bf[nj2][3]);
                }
        }

        // ---- store tile i+1 into xh[b^1] ----
        if (have_next) {
            char* dst = sm + (b ? XH0_OFF : XH1_OFF);
#pragma unroll
            for (int j = 0; j < 8; j++) {
                __half2 h0 = __floats2half2_rn(rv[j].x, rv[j].y);
                __half2 h1 = __floats2half2_rn(rv[j].z, rv[j].w);
                uint2 u = { *(unsigned*)&h0, *(unsigned*)&h1 };
                *(uint2*)(dst + (size_t)(cv_r0 + 16 * j) * (WSTR * 2) + cv_cc * 8) = u;
            }
        }

        // ---- epilogue: bias + hw-tanh + dot(W2) -> per-row partials ----
        float b1v[4][2], w2v[4][2];
#pragma unroll
        for (int nj = 0; nj < 4; nj++)
#pragma unroll
            for (int cc = 0; cc < 2; cc++) {
                float2 bw = bwp[n0 + nj * 8 + tig * 2 + cc];
                b1v[nj][cc] = bw.x;
                w2v[nj][cc] = bw.y;
            }
        float rp[4] = {0.0f, 0.0f, 0.0f, 0.0f};
#pragma unroll
        for (int mi = 0; mi < 2; mi++)
#pragma unroll
            for (int nj = 0; nj < 4; nj++)
#pragma unroll
                for (int r = 0; r < 4; r++) {
                    float h = tanh_hw(c[mi][nj][r] + b1v[nj][r & 1]);
                    rp[mi * 2 + (r >> 1)] = fmaf(h, w2v[nj][r & 1], rp[mi * 2 + (r >> 1)]);
                }
#pragma unroll
        for (int q = 0; q < 4; q++) {
            rp[q] += __shfl_xor_sync(0xffffffffu, rp[q], 1);
            rp[q] += __shfl_xor_sync(0xffffffffu, rp[q], 2);
        }
        if (tig == 0) {
#pragma unroll
            for (int q = 0; q < 4; q++) {
                int row = m0 + (q >> 1) * 16 + (q & 1) * 8 + gid;
                sred2[ph][ngrp][row] = rp[q];
            }
        }
        __syncthreads();   // the ONLY barrier per tile

        // ---- score out: sum 4 banks, fire-and-forget segment atomicMax ----
        if (tid < 128) {
            float sv = sred2[ph][0][tid] + sred2[ph][1][tid]
                     + sred2[ph][2][tid] + sred2[ph][3][tid] + b2v;
            g_s[row0 + tid] = sv;
            atomicMax(&g_segmaxb[myseg], fmap(sv));
        }
    }
}

// ---------------------------------------------------------------------------
// k2: e = exp(s - seg_max[idx]); smem bucket aggregation of seg_sum.
// 2048-row blocks (977 blocks).
// ---------------------------------------------------------------------------
__global__ __launch_bounds__(256) void k2_exp(
    const void* __restrict__ idxp, float* __restrict__ e_out)
{
    __shared__ float buck[2048];
    const int tid = threadIdx.x;
    const long long base = (long long)blockIdx.x * 2048;
    const long long last = min(base + 2047LL, (long long)NROWS - 1);
    const int is64 = g_is64;
    const int seg_lo = seg_at(idxp, is64, base);
    const int seg_hi = seg_at(idxp, is64, last);
    const int range = seg_hi - seg_lo + 1;
    const bool use_smem = (range > 0 && range <= 2048);
    if (use_smem)
        for (int k = tid; k < range; k += 256) buck[k] = 0.0f;
    __syncthreads();

    for (int j = tid; j < 2048; j += 256) {
        long long r = base + j;
        if (r >= NROWS) break;
        int seg = seg_at(idxp, is64, r);
        float smax = funmap(g_segmaxb[seg]);
        float e = __expf(g_s[r] - smax);
        e_out[r] = e;
        if (use_smem) atomicAdd(&buck[seg - seg_lo], e);
        else          atomicAdd(&g_segsum[seg], e);
    }
    __syncthreads();

    if (use_smem)
        for (int k = tid; k < range; k += 256) {
            float v = buck[k];
            if (v != 0.0f) atomicAdd(&g_segsum[seg_lo + k], v);
        }
}

// ---------------------------------------------------------------------------
// k3: alpha = e/(seg_sum+1e-16); out += x*alpha. FROZEN: simple fp32 loop
// (ptxas load batching), single-segment fast path, measured 183us @ 73% DRAM.
// ---------------------------------------------------------------------------
__global__ __launch_bounds__(128) void k3_agg(
    const float* __restrict__ x, const void* __restrict__ idxp,
    float* __restrict__ alpha, float* __restrict__ out)
{
    __shared__ float sa[512];
    __shared__ int   sseg[512];
    const int tid = threadIdx.x;
    const long long base = (long long)blockIdx.x * 512;
    const int nrows = (int)min(512LL, (long long)NROWS - base);
    const int is64 = g_is64;

    for (int j = tid; j < nrows; j += 128) {
        int seg = seg_at(idxp, is64, base + j);
        float e = alpha[base + j];
        float a = __fdividef(e, g_segsum[seg] + 1e-16f);
        sa[j] = a;
        sseg[j] = seg;
        alpha[base + j] = a;
    }
    __syncthreads();

    if (sseg[0] == sseg[nrows - 1]) {
        // fast path: whole block in one segment, no per-row seg checks
        float acc = 0.0f;
        for (int j = 0; j < nrows; j++)
            acc = fmaf(x[(size_t)(base + j) * D + tid], sa[j], acc);
        atomicAdd(&out[(size_t)sseg[0] * D + tid], acc);
    } else {
        float acc = 0.0f;
        int cur = sseg[0];
        for (int j = 0; j < nrows; j++) {
            int sg = sseg[j];
            if (sg != cur) {
                atomicAdd(&out[(size_t)cur * D + tid], acc);
                acc = 0.0f;
                cur = sg;
            }
            acc = fmaf(x[(size_t)(base + j) * D + tid], sa[j], acc);
        }
        atomicAdd(&out[(size_t)cur * D + tid], acc);
    }
}

// ---------------------------------------------------------------------------
extern "C" void kernel_launch(void* const* d_in, const int* in_sizes, int n_in,
                              void* d_out, int out_size)
{
    const float* x  = (const float*)d_in[0];
    const float* W1 = (const float*)d_in[1];
    const float* b1 = (const float*)d_in[2];
    const float* W2 = (const float*)d_in[3];
    const float* b2 = (const float*)d_in[4];
    const void*  idxp = d_in[5];

    float* outp  = (float*)d_out;          // (4096, 128)
    float* alpha = outp + NSEG * D;        // (N, 1) -- holds e between k2/k3

    static int sms = 0;
    if (!sms) {
        cudaDeviceGetAttribute(&sms, cudaDevAttrMultiProcessorCount, 0);
        cudaFuncSetAttribute(k1_mlp, cudaFuncAttributeMaxDynamicSharedMemorySize,
                             SMEM_TOTAL);
    }

    k0_init<<<(NSEG * D + 255) / 256, 256>>>(outp, idxp, W1);
    k1_mlp <<<sms, 512, SMEM_TOTAL>>>(x, b1, W2, b2, idxp);
    k2_exp <<<(NROWS + 2047) / 2048, 256>>>(idxp, alpha);
    k3_agg <<<(NROWS + 511) / 512, 128>>>(x, idxp, alpha, outp);
}

// round 17
// speedup vs baseline: 1.1986x; 1.0250x over previous
#include <cuda_runtime.h>
#include <cuda_fp16.h>
#include <cstdint>

#define NROWS 2000000
#define D 128
#define NSEG 4096
#define NTILES (NROWS / 128)          // 15625

// ---- k1 dynamic smem layout (bytes) ----
#define WS_OFF    0
#define XH0_OFF   34816
#define XH1_OFF   69632
#define MISC_OFF  104448
#define SMEM_TOTAL (104448 + 5120)

#define WSTR 136   // half stride of ws/xh rows (272 B)

// ---- scratch (no allocations allowed) ----
__device__ float    g_s[NROWS];
__device__ float    g_segsum[NSEG];
__device__ unsigned g_segmaxb[NSEG];
__device__ int      g_is64;
__device__ __half   g_w1h[D * D];   // W1^T as half: g_w1h[n*128+k] = W1[k][n]

// ---- helpers ----
__device__ __forceinline__ int seg_at(const void* p, int is64, long long i) {
    int v = is64 ? (int)((const long long*)p)[i] : ((const int*)p)[i];
    return min(max(v, 0), NSEG - 1);
}
__device__ __forceinline__ unsigned fmap(float f) {
    unsigned u = __float_as_uint(f);
    return (u & 0x80000000u) ? ~u : (u | 0x80000000u);
}
__device__ __forceinline__ float funmap(unsigned m) {
    return (m & 0x80000000u) ? __uint_as_float(m ^ 0x80000000u)
                             : __uint_as_float(~m);
}
__device__ __forceinline__ float tanh_hw(float v) {
    float r;
    asm("tanh.approx.f32 %0, %1;" : "=f"(r) : "f"(v));
    return r;
}
__device__ __forceinline__ void cp16(unsigned saddr, const void* g) {
    asm volatile("cp.async.cg.shared.global [%0], [%1], 16;\n"
                 :: "r"(saddr), "l"(g) : "memory");
}
__device__ __forceinline__ void cp_commit() {
    asm volatile("cp.async.commit_group;\n" ::: "memory");
}
__device__ __forceinline__ void cp_wait0() {
    asm volatile("cp.async.wait_group 0;\n" ::: "memory");
}
__device__ __forceinline__ void ldsm4(unsigned r[4], unsigned saddr) {
    asm volatile("ldmatrix.sync.aligned.m8n8.x4.shared.b16 {%0,%1,%2,%3}, [%4];\n"
                 : "=r"(r[0]), "=r"(r[1]), "=r"(r[2]), "=r"(r[3]) : "r"(saddr));
}
__device__ __forceinline__ void mma16816(float c[4], const unsigned a[4],
                                         unsigned b0, unsigned b1) {
    asm volatile(
        "mma.sync.aligned.m16n8k16.row.col.f32.f16.f16.f32 "
        "{%0,%1,%2,%3}, {%4,%5,%6,%7}, {%8,%9}, {%0,%1,%2,%3};\n"
        : "+f"(c[0]), "+f"(c[1]), "+f"(c[2]), "+f"(c[3])
        : "r"(a[0]), "r"(a[1]), "r"(a[2]), "r"(a[3]), "r"(b0), "r"(b1));
}

// ---------------------------------------------------------------------------
// k0: zero out + seg scratch; detect idx dtype; pack W1^T as half (n-major).
// ---------------------------------------------------------------------------
__global__ void k0_init(float* __restrict__ out, const void* __restrict__ idxp,
                        const float* __restrict__ W1) {
    long long i = (long long)blockIdx.x * blockDim.x + threadIdx.x;
    if (i < NSEG * D) out[i] = 0.0f;
    if (i < NSEG) { g_segsum[i] = 0.0f; g_segmaxb[i] = 0u; }
    if (i < D * D) {
        int n = (int)(i / D), k = (int)(i % D);
        g_w1h[i] = __float2half_rn(W1[(size_t)k * D + n]);
    }
    if (i == 0) {
        const long long* p64 = (const long long*)idxp;
        long long a = p64[NROWS / 4];
        long long b = p64[NROWS / 8];
        g_is64 = (a >= 0 && a < NSEG && b >= 0 && b < NSEG) ? 1 : 0;
    }
}

// ---------------------------------------------------------------------------
// k1: persistent fp16-mma MLP with CROSS-TILE DEFERRED EPILOGUE: iteration i
// runs MMA(i) with tile (i-1)'s tanh/dot interleaved into the k-steps (MUFU
// rides the HMMA shadow). Scoreout(i-1) post-barrier. One barrier per tile.
// ---------------------------------------------------------------------------
__global__ __launch_bounds__(512, 1)
void k1_mlp(const float* __restrict__ x,
            const float* __restrict__ b1, const float* __restrict__ W2,
            const float* __restrict__ b2, const void* __restrict__ idxp)
{
    extern __shared__ char sm[];
    float2* bwp = (float2*)(sm + MISC_OFF);
    float (*sred2)[4][128] = (float(*)[4][128])(sm + MISC_OFF + 1024);

    const unsigned s_base  = (unsigned)__cvta_generic_to_shared(sm);
    const unsigned s_ws    = s_base + WS_OFF;
    const unsigned s_xh[2] = { s_base + XH0_OFF, s_base + XH1_OFF };

    const int tid  = threadIdx.x;
    const int lane = tid & 31;
    const int warp = tid >> 5;
    const int gid  = lane >> 2;
    const int tig  = lane & 3;
    const int m0   = (warp & 3) * 32;
    const int n0   = (warp >> 2) * 32;
    const int ngrp = warp >> 2;
    const int grid = gridDim.x;
    const int cta  = blockIdx.x;
    const int n_t  = (NTILES - cta + grid - 1) / grid;
    const int is64 = g_is64;

    const int cv_r0 = tid >> 5;
    const int cv_cc = tid & 31;

    const unsigned a_off = (unsigned)((m0 + (lane & 15)) * (WSTR * 2) + ((lane >> 4) * 16));
    const unsigned b_off = (unsigned)((n0 + (lane & 7) + ((lane >> 4) << 3)) * (WSTR * 2)
                                      + (((lane >> 3) & 1) * 16));

    if (tid < 128) bwp[tid] = make_float2(b1[tid], W2[tid]);
    const float b2v = b2[0];

    if (n_t == 0) return;

    // ---- prologue: ws via cp.async (one-time), tile0 via LDG->cvt->STS ----
#pragma unroll
    for (int c = 0; c < 4; c++) {
        int q = tid + c * 512;
        int r = q >> 4, cc = q & 15;
        cp16(s_ws + (unsigned)(r * (WSTR * 2) + cc * 16),
             g_w1h + (size_t)r * D + cc * 8);
    }
    cp_commit();
    {
        const float4* xb = (const float4*)(x + (size_t)cta * 128 * D);
        float4 rv[8];
#pragma unroll
        for (int j = 0; j < 8; j++) rv[j] = xb[tid + j * 512];
        cp_wait0();
        __syncthreads();
#pragma unroll
        for (int j = 0; j < 8; j++) {
            __half2 h0 = __floats2half2_rn(rv[j].x, rv[j].y);
            __half2 h1 = __floats2half2_rn(rv[j].z, rv[j].w);
            uint2 u = { *(unsigned*)&h0, *(unsigned*)&h1 };
            *(uint2*)(sm + XH0_OFF + (size_t)(cv_r0 + 16 * j) * (WSTR * 2) + cv_cc * 8) = u;
        }
        __syncthreads();
    }

    float  c_prev[2][4][4];
    int    seg_prev = 0;
    size_t row0_prev = 0;

    for (int i = 0; i < n_t; i++) {
        const int b = i & 1;
        const unsigned xa = s_xh[b] + a_off;
        const unsigned bb = s_ws + b_off;
        const bool have_next = (i + 1 < n_t);
        const bool have_prev = (i > 0);
        const size_t row0 = ((size_t)cta + (size_t)i * grid) * 128;

        int seg_i = 0;
        if (tid < 128) seg_i = seg_at(idxp, is64, (long long)(row0 + tid));

        float c_cur[2][4][4];
#pragma unroll
        for (int mi = 0; mi < 2; mi++)
#pragma unroll
            for (int nj = 0; nj < 4; nj++)
#pragma unroll
                for (int r = 0; r < 4; r++) c_cur[mi][nj][r] = 0.0f;

        float rp[4] = {0.0f, 0.0f, 0.0f, 0.0f};
        float4 rv[8];

        // ---- k-steps 0..3: MMA + interleaved deferred epilogue (mi=0) ----
#pragma unroll
        for (int k0 = 0; k0 < 4; k0++) {
            unsigned af[2][4], bf[2][4];
            ldsm4(af[0], xa + k0 * 32);
            ldsm4(af[1], xa + 16 * (WSTR * 2) + k0 * 32);
            ldsm4(bf[0], bb + k0 * 32);
            ldsm4(bf[1], bb + 16 * (WSTR * 2) + k0 * 32);
#pragma unroll
            for (int mi = 0; mi < 2; mi++)
#pragma unroll
                for (int nj2 = 0; nj2 < 2; nj2++) {
                    mma16816(c_cur[mi][nj2 * 2],     af[mi], bf[nj2][0], bf[nj2][1]);
                    mma16816(c_cur[mi][nj2 * 2 + 1], af[mi], bf[nj2][2], bf[nj2][3]);
                }
            if (have_prev) {
                const int nj = k0;
                float2 bw0 = bwp[n0 + nj * 8 + tig * 2];
                float2 bw1 = bwp[n0 + nj * 8 + tig * 2 + 1];
#pragma unroll
                for (int r = 0; r < 4; r++) {
                    float h = tanh_hw(c_prev[0][nj][r] + ((r & 1) ? bw1.x : bw0.x));
                    rp[r >> 1] = fmaf(h, (r & 1) ? bw1.y : bw0.y, rp[r >> 1]);
                }
            }
        }

        // ---- mid-loop: issue next-tile x loads (c_prev half-dead now) ----
        if (have_next) {
            const float4* xn = (const float4*)(x + ((size_t)cta + (size_t)(i + 1) * grid) * 128 * D);
#pragma unroll
            for (int j = 0; j < 8; j++) rv[j] = xn[tid + j * 512];
        }

        // ---- k-steps 4..7: MMA + interleaved deferred epilogue (mi=1) ----
#pragma unroll
        for (int k0 = 4; k0 < 8; k0++) {
            unsigned af[2][4], bf[2][4];
            ldsm4(af[0], xa + k0 * 32);
            ldsm4(af[1], xa + 16 * (WSTR * 2) + k0 * 32);
            ldsm4(bf[0], bb + k0 * 32);
            ldsm4(bf[1], bb + 16 * (WSTR * 2) + k0 * 32);
#pragma unroll
            for (int mi = 0; mi < 2; mi++)
#pragma unroll
                for (int nj2 = 0; nj2 < 2; nj2++) {
                    mma16816(c_cur[mi][nj2 * 2],     af[mi], bf[nj2][0], bf[nj2][1]);
                    mma16816(c_cur[mi][nj2 * 2 + 1], af[mi], bf[nj2][2], bf[nj2][3]);
                }
            if (have_prev) {
                const int nj = k0 - 4;
                float2 bw0 = bwp[n0 + nj * 8 + tig * 2];
                float2 bw1 = bwp[n0 + nj * 8 + tig * 2 + 1];
#pragma unroll
                for (int r = 0; r < 4; r++) {
                    float h = tanh_hw(c_prev[1][nj][r] + ((r & 1) ? bw1.x : bw0.x));
                    rp[2 + (r >> 1)] = fmaf(h, (r & 1) ? bw1.y : bw0.y, rp[2 + (r >> 1)]);
                }
            }
        }

        // ---- reduce + sred store for tile i-1 (bank (i-1)&1) ----
        if (have_prev) {
#pragma unroll
            for (int q = 0; q < 4; q++) {
                rp[q] += __shfl_xor_sync(0xffffffffu, rp[q], 1);
                rp[q] += __shfl_xor_sync(0xffffffffu, rp[q], 2);
            }
            if (tig == 0) {
#pragma unroll
                for (int q = 0; q < 4; q++) {
                    int row = m0 + (q >> 1) * 16 + (q & 1) * 8 + gid;
                    sred2[(i - 1) & 1][ngrp][row] = rp[q];
                }
            }
        }

        // ---- store tile i+1 into xh[b^1] ----
        if (have_next) {
            char* dst = sm + (b ? XH0_OFF : XH1_OFF);
#pragma unroll
            for (int j = 0; j < 8; j++) {
                __half2 h0 = __floats2half2_rn(rv[j].x, rv[j].y);
                __half2 h1 = __floats2half2_rn(rv[j].z, rv[j].w);
                uint2 u = { *(unsigned*)&h0, *(unsigned*)&h1 };
                *(uint2*)(dst + (size_t)(cv_r0 + 16 * j) * (WSTR * 2) + cv_cc * 8) = u;
            }
        }

        __syncthreads();   // the ONLY barrier per tile

        // ---- scoreout tile i-1: sum banks, g_s write, atomicMax ----
        if (have_prev && tid < 128) {
            const int ph = (i - 1) & 1;
            float sv = sred2[ph][0][tid] + sred2[ph][1][tid]
                     + sred2[ph][2][tid] + sred2[ph][3][tid] + b2v;
            g_s[row0_prev + tid] = sv;
            atomicMax(&g_segmaxb[seg_prev], fmap(sv));
        }

        // ---- rotate pipeline state ----
#pragma unroll
        for (int mi = 0; mi < 2; mi++)
#pragma unroll
            for (int nj = 0; nj < 4; nj++)
#pragma unroll
                for (int r = 0; r < 4; r++) c_prev[mi][nj][r] = c_cur[mi][nj][r];
        seg_prev = seg_i;
        row0_prev = row0;
    }

    // ---- drain: epilogue + scoreout of the last tile ----
    {
        float rp[4] = {0.0f, 0.0f, 0.0f, 0.0f};
#pragma unroll
        for (int mi = 0; mi < 2; mi++)
#pragma unroll
            for (int nj = 0; nj < 4; nj++) {
                float2 bw0 = bwp[n0 + nj * 8 + tig * 2];
                float2 bw1 = bwp[n0 + nj * 8 + tig * 2 + 1];
#pragma unroll
                for (int r = 0; r < 4; r++) {
                    float h = tanh_hw(c_prev[mi][nj][r] + ((r & 1) ? bw1.x : bw0.x));
                    rp[mi * 2 + (r >> 1)] = fmaf(h, (r & 1) ? bw1.y : bw0.y,
                                                 rp[mi * 2 + (r >> 1)]);
                }
            }
#pragma unroll
        for (int q = 0; q < 4; q++) {
            rp[q] += __shfl_xor_sync(0xffffffffu, rp[q], 1);
            rp[q] += __shfl_xor_sync(0xffffffffu, rp[q], 2);
        }
        const int ph = (n_t - 1) & 1;
        if (tig == 0) {
#pragma unroll
            for (int q = 0; q < 4; q++) {
                int row = m0 + (q >> 1) * 16 + (q & 1) * 8 + gid;
                sred2[ph][ngrp][row] = rp[q];
            }
        }
        __syncthreads();
        if (tid < 128) {
            float sv = sred2[ph][0][tid] + sred2[ph][1][tid]
                     + sred2[ph][2][tid] + sred2[ph][3][tid] + b2v;
            g_s[row0_prev + tid] = sv;
            atomicMax(&g_segmaxb[seg_prev], fmap(sv));
        }
    }
}

// ---------------------------------------------------------------------------
// k2: e = exp(s - seg_max[idx]); smem bucket aggregation of seg_sum.
// ---------------------------------------------------------------------------
__global__ __launch_bounds__(256) void k2_exp(
    const void* __restrict__ idxp, float* __restrict__ e_out)
{
    __shared__ float buck[2048];
    const int tid = threadIdx.x;
    const long long base = (long long)blockIdx.x * 2048;
    const long long last = min(base + 2047LL, (long long)NROWS - 1);
    const int is64 = g_is64;
    const int seg_lo = seg_at(idxp, is64, base);
    const int seg_hi = seg_at(idxp, is64, last);
    const int range = seg_hi - seg_lo + 1;
    const bool use_smem = (range > 0 && range <= 2048);
    if (use_smem)
        for (int k = tid; k < range; k += 256) buck[k] = 0.0f;
    __syncthreads();

    for (int j = tid; j < 2048; j += 256) {
        long long r = base + j;
        if (r >= NROWS) break;
        int seg = seg_at(idxp, is64, r);
        float smax = funmap(g_segmaxb[seg]);
        float e = __expf(g_s[r] - smax);
        e_out[r] = e;
        if (use_smem) atomicAdd(&buck[seg - seg_lo], e);
        else          atomicAdd(&g_segsum[seg], e);
    }
    __syncthreads();

    if (use_smem)
        for (int k = tid; k < range; k += 256) {
            float v = buck[k];
            if (v != 0.0f) atomicAdd(&g_segsum[seg_lo + k], v);
        }
}

// ---------------------------------------------------------------------------
// k3: alpha = e/(seg_sum+1e-16); out += x*alpha. FROZEN: simple fp32 loop
// (ptxas load batching), single-segment fast path, measured 183us @ 73% DRAM.
// ---------------------------------------------------------------------------
__global__ __launch_bounds__(128) void k3_agg(
    const float* __restrict__ x, const void* __restrict__ idxp,
    float* __restrict__ alpha, float* __restrict__ out)
{
    __shared__ float sa[512];
    __shared__ int   sseg[512];
    const int tid = threadIdx.x;
    const long long base = (long long)blockIdx.x * 512;
    const int nrows = (int)min(512LL, (long long)NROWS - base);
    const int is64 = g_is64;

    for (int j = tid; j < nrows; j += 128) {
        int seg = seg_at(idxp, is64, base + j);
        float e = alpha[base + j];
        float a = __fdividef(e, g_segsum[seg] + 1e-16f);
        sa[j] = a;
        sseg[j] = seg;
        alpha[base + j] = a;
    }
    __syncthreads();

    if (sseg[0] == sseg[nrows - 1]) {
        float acc = 0.0f;
        for (int j = 0; j < nrows; j++)
            acc = fmaf(x[(size_t)(base + j) * D + tid], sa[j], acc);
        atomicAdd(&out[(size_t)sseg[0] * D + tid], acc);
    } else {
        float acc = 0.0f;
        int cur = sseg[0];
        for (int j = 0; j < nrows; j++) {
            int sg = sseg[j];
            if (sg != cur) {
                atomicAdd(&out[(size_t)cur * D + tid], acc);
                acc = 0.0f;
                cur = sg;
            }
            acc = fmaf(x[(size_t)(base + j) * D + tid], sa[j], acc);
        }
        atomicAdd(&out[(size_t)cur * D + tid], acc);
    }
}

// ---------------------------------------------------------------------------
extern "C" void kernel_launch(void* const* d_in, const int* in_sizes, int n_in,
                              void* d_out, int out_size)
{
    const float* x  = (const float*)d_in[0];
    const float* W1 = (const float*)d_in[1];
    const float* b1 = (const float*)d_in[2];
    const float* W2 = (const float*)d_in[3];
    const float* b2 = (const float*)d_in[4];
    const void*  idxp = d_in[5];

    float* outp  = (float*)d_out;          // (4096, 128)
    float* alpha = outp + NSEG * D;        // (N, 1) -- holds e between k2/k3

    static int sms = 0;
    if (!sms) {
        cudaDeviceGetAttribute(&sms, cudaDevAttrMultiProcessorCount, 0);
        cudaFuncSetAttribute(k1_mlp, cudaFuncAttributeMaxDynamicSharedMemorySize,
                             SMEM_TOTAL);
    }

    k0_init<<<(NSEG * D + 255) / 256, 256>>>(outp, idxp, W1);
    k1_mlp <<<sms, 512, SMEM_TOTAL>>>(x, b1, W2, b2, idxp);
    k2_exp <<<(NROWS + 2047) / 2048, 256>>>(idxp, alpha);
    k3_agg <<<(NROWS + 511) / 512, 128>>>(x, idxp, alpha, outp);
}